// round 9
// baseline (speedup 1.0000x reference)
#include <cuda_runtime.h>
#include <cuda_bf16.h>
#include <math.h>
#include <stdint.h>

#define F_IN   128
#define H      64
#define HV     16
#define N_MAX  100000
#define E_MAX  1700000
#define G_MAX  4096
#define BN_EPS 1e-5f
#define SBS    1024

// ---------------- scratch (device globals: allocation-free) ----------------
__device__ __nv_bfloat16 g_bufA[(size_t)N_MAX * H];   // bf16 activations
__device__ __nv_bfloat16 g_bufB[(size_t)N_MAX * H];
__device__ float4 g_pooled[(size_t)G_MAX * HV];
__device__ float  g_dinv[N_MAX];
__device__ int    g_degcnt[N_MAX];
__device__ int    g_cursor[N_MAX];
__device__ int    g_incl[N_MAX];
__device__ int    g_bsum[SBS];
__device__ int    g_rowptr[N_MAX + 1];
__device__ int    g_csrc[E_MAX];
__device__ float  g_cw[E_MAX];
__device__ float  g_bnA[3 * H];
__device__ float  g_bnB[3 * H];

// ---------------- helpers ----------------
__device__ __forceinline__ uint32_t smem_u32(const void* p) {
    uint32_t a;
    asm("{ .reg .u64 t; cvta.to.shared.u64 t, %1; cvt.u32.u64 %0, t; }"
        : "=r"(a) : "l"(p));
    return a;
}
__device__ __forceinline__ void red_add_v4(float4* p, float4 v) {
    asm volatile("red.global.add.v4.f32 [%0], {%1, %2, %3, %4};"
                 :: "l"(p), "f"(v.x), "f"(v.y), "f"(v.z), "f"(v.w)
                 : "memory");
}
__device__ __forceinline__ void ldsm4(uint32_t* r, uint32_t addr) {
    asm volatile("ldmatrix.sync.aligned.m8n8.x4.shared.b16 {%0,%1,%2,%3}, [%4];"
                 : "=r"(r[0]), "=r"(r[1]), "=r"(r[2]), "=r"(r[3]) : "r"(addr));
}
__device__ __forceinline__ void mma_bf16(float* c, const uint32_t* a,
                                         const uint32_t* b) {
    asm volatile(
        "mma.sync.aligned.m16n8k16.row.col.f32.bf16.bf16.f32 "
        "{%0,%1,%2,%3}, {%4,%5,%6,%7}, {%8,%9}, {%0,%1,%2,%3};"
        : "+f"(c[0]), "+f"(c[1]), "+f"(c[2]), "+f"(c[3])
        : "r"(a[0]), "r"(a[1]), "r"(a[2]), "r"(a[3]), "r"(b[0]), "r"(b[1]));
}
__device__ __forceinline__ uint32_t pack_bf2(float lo, float hi) {
    __nv_bfloat162 r = __floats2bfloat162_rn(lo, hi);
    return *(uint32_t*)&r;
}

// ---------------- setup kernels ----------------
__global__ __launch_bounds__(256) void k_init(float4* pooled, int* degcnt,
                                              int* cursor, int n, int g) {
    int i = blockIdx.x * 256 + threadIdx.x;
    if (i < g * HV) pooled[i] = make_float4(0.f, 0.f, 0.f, 0.f);
    if (i < n) { degcnt[i] = 0; cursor[i] = 0; }
}

__global__ __launch_bounds__(256) void k_hist(const int* __restrict__ dst,
                                              int* degcnt, int e) {
    int i = blockIdx.x * 256 + threadIdx.x;
    if (i < e) atomicAdd(degcnt + __ldg(dst + i), 1);
}

__global__ __launch_bounds__(SBS) void k_scan1(const int* __restrict__ cnt,
                                               int* incl, int* bsum,
                                               float* dinv, int n) {
    __shared__ int sh[SBS];
    int i = blockIdx.x * SBS + threadIdx.x;
    int v = (i < n) ? cnt[i] : 0;
    if (i < n) dinv[i] = rsqrtf((float)v + 1.0f);
    sh[threadIdx.x] = v;
    __syncthreads();
    for (int off = 1; off < SBS; off <<= 1) {
        int t = (threadIdx.x >= off) ? sh[threadIdx.x - off] : 0;
        __syncthreads();
        sh[threadIdx.x] += t;
        __syncthreads();
    }
    if (i < n) incl[i] = sh[threadIdx.x];
    if (threadIdx.x == SBS - 1) bsum[blockIdx.x] = sh[SBS - 1];
}

__global__ __launch_bounds__(SBS) void k_scan2(int* bsum, int nb) {
    __shared__ int sh[SBS];
    int t = threadIdx.x;
    int v = (t < nb) ? bsum[t] : 0;
    sh[t] = v;
    __syncthreads();
    for (int off = 1; off < SBS; off <<= 1) {
        int u = (t >= off) ? sh[t - off] : 0;
        __syncthreads();
        sh[t] += u;
        __syncthreads();
    }
    if (t < nb) bsum[t] = sh[t] - v;
}

__global__ __launch_bounds__(256) void k_scan3(const int* __restrict__ incl,
                                               const int* __restrict__ bsum,
                                               int* rowptr, int n) {
    int i = blockIdx.x * 256 + threadIdx.x;
    if (i < n) rowptr[i + 1] = incl[i] + bsum[i / SBS];
    if (i == 0) rowptr[0] = 0;
}

__global__ __launch_bounds__(256) void k_fill(const int* __restrict__ src,
                                              const int* __restrict__ dst,
                                              const int* __restrict__ rowptr,
                                              const float* __restrict__ dinv,
                                              int* cursor, int* csrc,
                                              float* cw, int e) {
    int i = blockIdx.x * 256 + threadIdx.x;
    if (i >= e) return;
    int s = __ldg(src + i), d = __ldg(dst + i);
    int pos = __ldg(rowptr + d) + atomicAdd(cursor + d, 1);
    csrc[pos] = s;
    cw[pos] = __ldg(dinv + s) * __ldg(dinv + d);
}

__global__ void k_bn(const float* b0, const float* gg0, const float* be0,
                     const float* m0, const float* v0,
                     const float* b1, const float* gg1, const float* be1,
                     const float* m1, const float* v1,
                     const float* b2, const float* gg2, const float* be2,
                     const float* m2, const float* v2,
                     float* A, float* B) {
    int t = threadIdx.x;
    if (t >= 3 * H) return;
    int l = t >> 6, f = t & 63;
    const float* bs[3] = {b0, b1, b2};
    const float* gs[3] = {gg0, gg1, gg2};
    const float* es[3] = {be0, be1, be2};
    const float* ms[3] = {m0, m1, m2};
    const float* vs[3] = {v0, v1, v2};
    float a = gs[l][f] * rsqrtf(vs[l][f] + BN_EPS);
    A[t] = a;
    B[t] = es[l][f] + (bs[l][f] - ms[l][f]) * a;
}

// ---- layer-0 GEMM: fp32 X, bf16 hi/lo split (3 terms), bf16 output --------
template<int K>
__global__ __launch_bounds__(512) void k_gemm_f32(const float* __restrict__ X,
                                                  const float* __restrict__ W,
                                                  __nv_bfloat16* __restrict__ Y,
                                                  int n) {
    extern __shared__ __align__(16) char smem[];
    constexpr int LD = K + 8;
    __nv_bfloat16* Ah = (__nv_bfloat16*)smem;
    __nv_bfloat16* Al = Ah + 128 * LD;
    __nv_bfloat16* Bh = Al + 128 * LD;
    __nv_bfloat16* Bl = Bh + 64 * LD;

    const int t = threadIdx.x;
    const int wid = t >> 5, lane = t & 31;
    const int row0 = blockIdx.x * 128;

#pragma unroll
    for (int i = 0; i < 128 * (K / 4) / 512; i++) {
        int idx = t + i * 512;
        int r = idx / (K / 4);
        int k0 = (idx % (K / 4)) * 4;
        int gr = row0 + r;
        float4 v = make_float4(0.f, 0.f, 0.f, 0.f);
        if (gr < n) v = *(const float4*)(X + (size_t)gr * K + k0);
        float hx = __bfloat162float(__float2bfloat16(v.x));
        float hy = __bfloat162float(__float2bfloat16(v.y));
        float hz = __bfloat162float(__float2bfloat16(v.z));
        float hw = __bfloat162float(__float2bfloat16(v.w));
        uint2 hp, lp;
        hp.x = pack_bf2(v.x, v.y);
        hp.y = pack_bf2(v.z, v.w);
        lp.x = pack_bf2(v.x - hx, v.y - hy);
        lp.y = pack_bf2(v.z - hz, v.w - hw);
        *(uint2*)&Ah[r * LD + k0] = hp;
        *(uint2*)&Al[r * LD + k0] = lp;
    }
#pragma unroll
    for (int i = 0; i < K * 64 / 512; i++) {
        int idx = t + i * 512;
        int k = idx >> 6, nn = idx & 63;
        float w = W[(size_t)k * 64 + nn];
        float hh = __bfloat162float(__float2bfloat16(w));
        Bh[nn * LD + k] = __float2bfloat16(w);
        Bl[nn * LD + k] = __float2bfloat16(w - hh);
    }
    __syncthreads();

    float c[4][4];
#pragma unroll
    for (int j = 0; j < 4; j++) {
        c[j][0] = 0.f; c[j][1] = 0.f; c[j][2] = 0.f; c[j][3] = 0.f;
    }
    const int m0 = (wid >> 1) * 16;
    const int nb = (wid & 1) * 32;
    const uint32_t sAh = smem_u32(Ah), sAl = smem_u32(Al);
    const uint32_t sBh = smem_u32(Bh), sBl = smem_u32(Bl);
    uint32_t aOff = (uint32_t)(((m0 + (lane & 15)) * LD + ((lane >> 4) << 3)) * 2);
    uint32_t bOff = (uint32_t)(((nb + (lane & 7) + ((lane >> 4) << 3)) * LD
                                + (lane & 8)) * 2);

#pragma unroll
    for (int kc = 0; kc < K / 16; kc++) {
        uint32_t ah[4], al[4];
        ldsm4(ah, sAh + aOff + kc * 32);
        ldsm4(al, sAl + aOff + kc * 32);
#pragma unroll
        for (int j = 0; j < 2; j++) {
            uint32_t off = bOff + (uint32_t)(j * 16 * LD * 2) + kc * 32;
            uint32_t bh[4], bl[4];
            ldsm4(bh, sBh + off);
            ldsm4(bl, sBl + off);
            mma_bf16(c[2 * j],     ah, bh);
            mma_bf16(c[2 * j],     ah, bl);
            mma_bf16(c[2 * j],     al, bh);
            mma_bf16(c[2 * j + 1], ah, bh + 2);
            mma_bf16(c[2 * j + 1], ah, bl + 2);
            mma_bf16(c[2 * j + 1], al, bh + 2);
        }
    }

    int cr = lane >> 2, cc = (lane & 3) * 2;
    int r0g = row0 + m0 + cr;
    int r1g = r0g + 8;
    if (r0g < n) {
#pragma unroll
        for (int jj = 0; jj < 4; jj++)
            *(uint32_t*)(Y + (size_t)r0g * 64 + nb + jj * 8 + cc)
                = pack_bf2(c[jj][0], c[jj][1]);
    }
    if (r1g < n) {
#pragma unroll
        for (int jj = 0; jj < 4; jj++)
            *(uint32_t*)(Y + (size_t)r1g * 64 + nb + jj * 8 + cc)
                = pack_bf2(c[jj][2], c[jj][3]);
    }
}

// ---- layers 1/2 GEMM: bf16 X (exact), B hi/lo split (2 terms) -------------
__global__ __launch_bounds__(512) void k_gemm_bf(const __nv_bfloat16* __restrict__ X,
                                                 const float* __restrict__ W,
                                                 __nv_bfloat16* __restrict__ Y,
                                                 int n) {
    constexpr int K = 64;
    extern __shared__ __align__(16) char smem[];
    constexpr int LD = K + 8;
    __nv_bfloat16* Ah = (__nv_bfloat16*)smem;     // [128][LD]
    __nv_bfloat16* Bh = Ah + 128 * LD;            // [64][LD]
    __nv_bfloat16* Bl = Bh + 64 * LD;

    const int t = threadIdx.x;
    const int wid = t >> 5, lane = t & 31;
    const int row0 = blockIdx.x * 128;

#pragma unroll
    for (int i = 0; i < 4; i++) {
        int idx = t + i * 512;
        int r = idx >> 4;
        int k0 = (idx & 15) * 4;
        int gr = row0 + r;
        uint2 v = make_uint2(0u, 0u);
        if (gr < n) v = *(const uint2*)(X + (size_t)gr * K + k0);
        *(uint2*)&Ah[r * LD + k0] = v;
    }
#pragma unroll
    for (int i = 0; i < K * 64 / 512; i++) {
        int idx = t + i * 512;
        int k = idx >> 6, nn = idx & 63;
        float w = W[(size_t)k * 64 + nn];
        float hh = __bfloat162float(__float2bfloat16(w));
        Bh[nn * LD + k] = __float2bfloat16(w);
        Bl[nn * LD + k] = __float2bfloat16(w - hh);
    }
    __syncthreads();

    float c[4][4];
#pragma unroll
    for (int j = 0; j < 4; j++) {
        c[j][0] = 0.f; c[j][1] = 0.f; c[j][2] = 0.f; c[j][3] = 0.f;
    }
    const int m0 = (wid >> 1) * 16;
    const int nb = (wid & 1) * 32;
    const uint32_t sAh = smem_u32(Ah);
    const uint32_t sBh = smem_u32(Bh), sBl = smem_u32(Bl);
    uint32_t aOff = (uint32_t)(((m0 + (lane & 15)) * LD + ((lane >> 4) << 3)) * 2);
    uint32_t bOff = (uint32_t)(((nb + (lane & 7) + ((lane >> 4) << 3)) * LD
                                + (lane & 8)) * 2);

#pragma unroll
    for (int kc = 0; kc < K / 16; kc++) {
        uint32_t ah[4];
        ldsm4(ah, sAh + aOff + kc * 32);
#pragma unroll
        for (int j = 0; j < 2; j++) {
            uint32_t off = bOff + (uint32_t)(j * 16 * LD * 2) + kc * 32;
            uint32_t bh[4], bl[4];
            ldsm4(bh, sBh + off);
            ldsm4(bl, sBl + off);
            mma_bf16(c[2 * j],     ah, bh);
            mma_bf16(c[2 * j],     ah, bl);
            mma_bf16(c[2 * j + 1], ah, bh + 2);
            mma_bf16(c[2 * j + 1], ah, bl + 2);
        }
    }

    int cr = lane >> 2, cc = (lane & 3) * 2;
    int r0g = row0 + m0 + cr;
    int r1g = r0g + 8;
    if (r0g < n) {
#pragma unroll
        for (int jj = 0; jj < 4; jj++)
            *(uint32_t*)(Y + (size_t)r0g * 64 + nb + jj * 8 + cc)
                = pack_bf2(c[jj][0], c[jj][1]);
    }
    if (r1g < n) {
#pragma unroll
        for (int jj = 0; jj < 4; jj++)
            *(uint32_t*)(Y + (size_t)r1g * 64 + nb + jj * 8 + cc)
                = pack_bf2(c[jj][2], c[jj][3]);
    }
}

// --------- fused gather + self-loop + BN + ReLU (+pool), 4-way ILP ---------
// Warp per node: 8 lanes x uint4 (16 bf16 bytes) per edge, 4 edge parities
// in flight (c = lane&7, p = lane>>3). Halves loop trips vs the 2-parity
// form and doubles independent L2 load chains per warp.
template<bool POOL>
__global__ __launch_bounds__(512) void k_gather(const int* __restrict__ rowptr,
                                                const int* __restrict__ csrc,
                                                const float* __restrict__ cw,
                                                const float* __restrict__ dinv,
                                                const __nv_bfloat16* __restrict__ h,
                                                __nv_bfloat16* __restrict__ y,
                                                const float* __restrict__ bnA,
                                                const float* __restrict__ bnB,
                                                const int* __restrict__ batch,
                                                float4* pooled, int n) {
    int node = blockIdx.x * 16 + (threadIdx.x >> 5);
    if (node >= n) return;
    int lane = threadIdx.x & 31;
    int c = lane & 7, p = lane >> 3;
    int beg = __ldg(rowptr + node), end = __ldg(rowptr + node + 1);

    const uint4* h4 = (const uint4*)h;      // 8 uint4 per 64-feature row

    float a0 = 0.f, a1 = 0.f, a2 = 0.f, a3 = 0.f;
    float a4 = 0.f, a5 = 0.f, a6 = 0.f, a7 = 0.f;
#pragma unroll 2
    for (int j = beg + p; j < end; j += 4) {
        int s = __ldg(csrc + j);
        float w = __ldg(cw + j);
        uint4 u = __ldg(h4 + (size_t)s * 8 + c);
        float2 f0 = __bfloat1622float2(*(__nv_bfloat162*)&u.x);
        float2 f1 = __bfloat1622float2(*(__nv_bfloat162*)&u.y);
        float2 f2 = __bfloat1622float2(*(__nv_bfloat162*)&u.z);
        float2 f3 = __bfloat1622float2(*(__nv_bfloat162*)&u.w);
        a0 = fmaf(f0.x, w, a0); a1 = fmaf(f0.y, w, a1);
        a2 = fmaf(f1.x, w, a2); a3 = fmaf(f1.y, w, a3);
        a4 = fmaf(f2.x, w, a4); a5 = fmaf(f2.y, w, a5);
        a6 = fmaf(f3.x, w, a6); a7 = fmaf(f3.y, w, a7);
    }
    // combine 4 parities: lanes 0-7 end with the full sums
    a0 += __shfl_down_sync(0xffffffffu, a0, 16);
    a1 += __shfl_down_sync(0xffffffffu, a1, 16);
    a2 += __shfl_down_sync(0xffffffffu, a2, 16);
    a3 += __shfl_down_sync(0xffffffffu, a3, 16);
    a4 += __shfl_down_sync(0xffffffffu, a4, 16);
    a5 += __shfl_down_sync(0xffffffffu, a5, 16);
    a6 += __shfl_down_sync(0xffffffffu, a6, 16);
    a7 += __shfl_down_sync(0xffffffffu, a7, 16);
    a0 += __shfl_down_sync(0xffffffffu, a0, 8);
    a1 += __shfl_down_sync(0xffffffffu, a1, 8);
    a2 += __shfl_down_sync(0xffffffffu, a2, 8);
    a3 += __shfl_down_sync(0xffffffffu, a3, 8);
    a4 += __shfl_down_sync(0xffffffffu, a4, 8);
    a5 += __shfl_down_sync(0xffffffffu, a5, 8);
    a6 += __shfl_down_sync(0xffffffffu, a6, 8);
    a7 += __shfl_down_sync(0xffffffffu, a7, 8);

    if (lane < 8) {
        float di = __ldg(dinv + node);
        float d2 = di * di;
        uint4 u = __ldg(h4 + (size_t)node * 8 + lane);
        float2 h0 = __bfloat1622float2(*(__nv_bfloat162*)&u.x);
        float2 h1 = __bfloat1622float2(*(__nv_bfloat162*)&u.y);
        float2 h2 = __bfloat1622float2(*(__nv_bfloat162*)&u.z);
        float2 h3 = __bfloat1622float2(*(__nv_bfloat162*)&u.w);
        float4 A0 = *(const float4*)(bnA + lane * 8);
        float4 A1 = *(const float4*)(bnA + lane * 8 + 4);
        float4 B0 = *(const float4*)(bnB + lane * 8);
        float4 B1 = *(const float4*)(bnB + lane * 8 + 4);
        float o0 = fmaxf(fmaf(fmaf(h0.x, d2, a0), A0.x, B0.x), 0.f);
        float o1 = fmaxf(fmaf(fmaf(h0.y, d2, a1), A0.y, B0.y), 0.f);
        float o2 = fmaxf(fmaf(fmaf(h1.x, d2, a2), A0.z, B0.z), 0.f);
        float o3 = fmaxf(fmaf(fmaf(h1.y, d2, a3), A0.w, B0.w), 0.f);
        float o4 = fmaxf(fmaf(fmaf(h2.x, d2, a4), A1.x, B1.x), 0.f);
        float o5 = fmaxf(fmaf(fmaf(h2.y, d2, a5), A1.y, B1.y), 0.f);
        float o6 = fmaxf(fmaf(fmaf(h3.x, d2, a6), A1.z, B1.z), 0.f);
        float o7 = fmaxf(fmaf(fmaf(h3.y, d2, a7), A1.w, B1.w), 0.f);
        uint4 ob;
        ob.x = pack_bf2(o0, o1);
        ob.y = pack_bf2(o2, o3);
        ob.z = pack_bf2(o4, o5);
        ob.w = pack_bf2(o6, o7);
        ((uint4*)(y + (size_t)node * 64))[lane] = ob;
        if (POOL) {
            float4* pr = pooled + (size_t)__ldg(batch + node) * HV + lane * 2;
            red_add_v4(pr,     make_float4(o0, o1, o2, o3));
            red_add_v4(pr + 1, make_float4(o4, o5, o6, o7));
        }
    }
}

// ---------------- readout MLP ----------------
__global__ __launch_bounds__(256) void k_mlp(const float* __restrict__ pooled,
                                             const float* __restrict__ l1w,
                                             const float* __restrict__ l1b,
                                             const float* __restrict__ l2w,
                                             const float* __restrict__ l2b,
                                             float* __restrict__ out, int g) {
    __shared__ float4 W1[64 * 8];
    __shared__ float  B1[32];
    __shared__ float  W2[64];
    __shared__ float  B2[2];
    int t = threadIdx.x;
    for (int idx = t; idx < 512; idx += 256) W1[idx] = ((const float4*)l1w)[idx];
    if (t < 32) B1[t] = l1b[t];
    if (t < 64) W2[t] = l2w[t];
    if (t < 2)  B2[t] = l2b[t];
    __syncthreads();

    int gi = blockIdx.x * 256 + t;
    if (gi >= g) return;

    float hid[32];
#pragma unroll
    for (int j = 0; j < 32; j++) hid[j] = B1[j];
    for (int k = 0; k < 64; k++) {
        float p = pooled[(size_t)gi * 64 + k];
#pragma unroll
        for (int jj = 0; jj < 8; jj++) {
            float4 w = W1[k * 8 + jj];
            hid[jj * 4 + 0] = fmaf(p, w.x, hid[jj * 4 + 0]);
            hid[jj * 4 + 1] = fmaf(p, w.y, hid[jj * 4 + 1]);
            hid[jj * 4 + 2] = fmaf(p, w.z, hid[jj * 4 + 2]);
            hid[jj * 4 + 3] = fmaf(p, w.w, hid[jj * 4 + 3]);
        }
    }
    float o0 = B2[0], o1 = B2[1];
#pragma unroll
    for (int j = 0; j < 32; j++) {
        float hj = fmaxf(hid[j], 0.f);
        o0 = fmaf(hj, W2[j * 2 + 0], o0);
        o1 = fmaf(hj, W2[j * 2 + 1], o1);
    }
    out[(size_t)gi * 2 + 0] = o0;
    out[(size_t)gi * 2 + 1] = o1;
}

// ---------------- launch ----------------
extern "C" void kernel_launch(void* const* d_in, const int* in_sizes, int n_in,
                              void* d_out, int out_size) {
    const float* x     = (const float*)d_in[0];
    const int*   ei    = (const int*)  d_in[1];
    const int*   batch = (const int*)  d_in[2];
    const float* w0 = (const float*)d_in[3];
    const float* b0 = (const float*)d_in[4];
    const float* w1 = (const float*)d_in[5];
    const float* b1 = (const float*)d_in[6];
    const float* w2 = (const float*)d_in[7];
    const float* b2 = (const float*)d_in[8];
    const float* gg0 = (const float*)d_in[9],  *be0 = (const float*)d_in[10];
    const float* m0  = (const float*)d_in[11], *v0  = (const float*)d_in[12];
    const float* gg1 = (const float*)d_in[13], *be1 = (const float*)d_in[14];
    const float* m1  = (const float*)d_in[15], *v1  = (const float*)d_in[16];
    const float* gg2 = (const float*)d_in[17], *be2 = (const float*)d_in[18];
    const float* m2  = (const float*)d_in[19], *v2  = (const float*)d_in[20];
    const float* l1w = (const float*)d_in[21], *l1b = (const float*)d_in[22];
    const float* l2w = (const float*)d_in[23], *l2b = (const float*)d_in[24];

    const int n = in_sizes[0] / F_IN;
    const int e = in_sizes[1] / 2;
    const int g = out_size / 2;
    if (n <= 0) return;

    __nv_bfloat16 *bufA, *bufB;
    float4 *pooled;
    float  *dinv, *cw, *bnA, *bnB;
    int    *degcnt, *cursor, *incl, *bsum, *rowptr, *csrc;
    cudaGetSymbolAddress((void**)&bufA,   g_bufA);
    cudaGetSymbolAddress((void**)&bufB,   g_bufB);
    cudaGetSymbolAddress((void**)&pooled, g_pooled);
    cudaGetSymbolAddress((void**)&dinv,   g_dinv);
    cudaGetSymbolAddress((void**)&degcnt, g_degcnt);
    cudaGetSymbolAddress((void**)&cursor, g_cursor);
    cudaGetSymbolAddress((void**)&incl,   g_incl);
    cudaGetSymbolAddress((void**)&bsum,   g_bsum);
    cudaGetSymbolAddress((void**)&rowptr, g_rowptr);
    cudaGetSymbolAddress((void**)&csrc,   g_csrc);
    cudaGetSymbolAddress((void**)&cw,     g_cw);
    cudaGetSymbolAddress((void**)&bnA,    g_bnA);
    cudaGetSymbolAddress((void**)&bnB,    g_bnB);

    const int* src = ei;
    const int* dst = ei + e;

    const int TB = 256;
    const int gInit = (((n > g * HV) ? n : g * HV) + TB - 1) / TB;
    const int gEdge = (e + TB - 1) / TB;
    const int gNode = (n + TB - 1) / TB;
    const int nbScan = (n + SBS - 1) / SBS;
    const int gGemm = (n + 127) / 128;
    const int gGath = (n + 15) / 16;

    const int SM128 = (128 * (F_IN + 8) * 2 + 64 * (F_IN + 8) * 2) * 2; // 104448
    const int SMBF  = (128 * (H + 8) + 2 * 64 * (H + 8)) * 2;           // 36864
    cudaFuncSetAttribute(k_gemm_f32<F_IN>,
                         cudaFuncAttributeMaxDynamicSharedMemorySize, SM128);
    cudaFuncSetAttribute(k_gemm_bf,
                         cudaFuncAttributeMaxDynamicSharedMemorySize, SMBF);

    static cudaStream_t s_pre = nullptr;
    static cudaEvent_t ev_fork = nullptr, ev_join = nullptr;
    if (s_pre == nullptr) {
        cudaStreamCreateWithFlags(&s_pre, cudaStreamNonBlocking);
        cudaEventCreateWithFlags(&ev_fork, cudaEventDisableTiming);
        cudaEventCreateWithFlags(&ev_join, cudaEventDisableTiming);
    }

    // ---- fork: graph preprocessing concurrent with gemm0 ----
    cudaEventRecord(ev_fork, 0);
    cudaStreamWaitEvent(s_pre, ev_fork, 0);
    k_init <<<gInit, TB, 0, s_pre>>>(pooled, degcnt, cursor, n, g);
    k_hist <<<gEdge, TB, 0, s_pre>>>(dst, degcnt, e);
    k_scan1<<<nbScan, SBS, 0, s_pre>>>(degcnt, incl, bsum, dinv, n);
    k_scan2<<<1, SBS, 0, s_pre>>>(bsum, nbScan);
    k_scan3<<<gNode, TB, 0, s_pre>>>(incl, bsum, rowptr, n);
    k_fill <<<gEdge, TB, 0, s_pre>>>(src, dst, rowptr, dinv, cursor, csrc, cw, e);
    cudaEventRecord(ev_join, s_pre);

    k_bn<<<1, 3 * H>>>(b0, gg0, be0, m0, v0, b1, gg1, be1, m1, v1,
                       b2, gg2, be2, m2, v2, bnA, bnB);
    k_gemm_f32<F_IN><<<gGemm, 512, SM128>>>(x, w0, bufA, n);

    cudaStreamWaitEvent(0, ev_join, 0);

    // ----- layer 0 gather -----
    k_gather<false><<<gGath, 512>>>(rowptr, csrc, cw, dinv, bufA, bufB,
                                    bnA, bnB, batch, pooled, n);
    // ----- layer 1 -----
    k_gemm_bf<<<gGemm, 512, SMBF>>>(bufB, w1, bufA, n);
    k_gather<false><<<gGath, 512>>>(rowptr, csrc, cw, dinv, bufA, bufB,
                                    bnA + H, bnB + H, batch, pooled, n);
    // ----- layer 2 (pool fused) -----
    k_gemm_bf<<<gGemm, 512, SMBF>>>(bufB, w2, bufA, n);
    k_gather<true><<<gGath, 512>>>(rowptr, csrc, cw, dinv, bufA, bufB,
                                   bnA + 2 * H, bnB + 2 * H, batch, pooled, n);

    // ----- readout MLP -----
    k_mlp<<<(g + TB - 1) / TB, TB>>>((const float*)pooled, l1w, l1b, l2w, l2b,
                                     (float*)d_out, g);
}

// round 11
// speedup vs baseline: 1.1587x; 1.1587x over previous
#include <cuda_runtime.h>
#include <cuda_bf16.h>
#include <math.h>
#include <stdint.h>

#define F_IN   128
#define H      64
#define HV     16
#define N_MAX  100000
#define E_MAX  1700000
#define G_MAX  4096
#define BN_EPS 1e-5f
#define SBS    1024

// ---------------- scratch (device globals: allocation-free) ----------------
__device__ __nv_bfloat16 g_bufA[(size_t)N_MAX * H];   // bf16 activations
__device__ __nv_bfloat16 g_bufB[(size_t)N_MAX * H];
__device__ float4 g_pooled[(size_t)G_MAX * HV];
__device__ float  g_dinv[N_MAX];
__device__ int    g_degcnt[N_MAX];
__device__ int    g_cursor[N_MAX];
__device__ int    g_incl[N_MAX];
__device__ int    g_bsum[SBS];
__device__ int    g_rowptr[N_MAX + 1];
__device__ uint2  g_edge[E_MAX];          // packed {src, weight}
__device__ float  g_bnA[3 * H];
__device__ float  g_bnB[3 * H];

// ---------------- helpers ----------------
__device__ __forceinline__ uint32_t smem_u32(const void* p) {
    uint32_t a;
    asm("{ .reg .u64 t; cvta.to.shared.u64 t, %1; cvt.u32.u64 %0, t; }"
        : "=r"(a) : "l"(p));
    return a;
}
__device__ __forceinline__ void red_add_v4(float4* p, float4 v) {
    asm volatile("red.global.add.v4.f32 [%0], {%1, %2, %3, %4};"
                 :: "l"(p), "f"(v.x), "f"(v.y), "f"(v.z), "f"(v.w)
                 : "memory");
}
__device__ __forceinline__ void ldsm4(uint32_t* r, uint32_t addr) {
    asm volatile("ldmatrix.sync.aligned.m8n8.x4.shared.b16 {%0,%1,%2,%3}, [%4];"
                 : "=r"(r[0]), "=r"(r[1]), "=r"(r[2]), "=r"(r[3]) : "r"(addr));
}
__device__ __forceinline__ void mma_bf16(float* c, const uint32_t* a,
                                         const uint32_t* b) {
    asm volatile(
        "mma.sync.aligned.m16n8k16.row.col.f32.bf16.bf16.f32 "
        "{%0,%1,%2,%3}, {%4,%5,%6,%7}, {%8,%9}, {%0,%1,%2,%3};"
        : "+f"(c[0]), "+f"(c[1]), "+f"(c[2]), "+f"(c[3])
        : "r"(a[0]), "r"(a[1]), "r"(a[2]), "r"(a[3]), "r"(b[0]), "r"(b[1]));
}
__device__ __forceinline__ uint32_t pack_bf2(float lo, float hi) {
    __nv_bfloat162 r = __floats2bfloat162_rn(lo, hi);
    return *(uint32_t*)&r;
}

// ---------------- setup kernels ----------------
__global__ __launch_bounds__(256) void k_init(float4* pooled, int* degcnt,
                                              int* cursor, int n, int g) {
    int i = blockIdx.x * 256 + threadIdx.x;
    if (i < g * HV) pooled[i] = make_float4(0.f, 0.f, 0.f, 0.f);
    if (i < n) { degcnt[i] = 0; cursor[i] = 0; }
}

__global__ __launch_bounds__(256) void k_hist(const int* __restrict__ dst,
                                              int* degcnt, int e) {
    int i = blockIdx.x * 256 + threadIdx.x;
    if (i < e) atomicAdd(degcnt + __ldg(dst + i), 1);
}

// warp-shuffle inclusive scan per block; per-block sums to bsum
__global__ __launch_bounds__(SBS) void k_scan1(const int* __restrict__ cnt,
                                               int* incl, int* bsum,
                                               float* dinv, int n) {
    __shared__ int wsum[32];
    int i = blockIdx.x * SBS + threadIdx.x;
    int lane = threadIdx.x & 31, w = threadIdx.x >> 5;
    int v = (i < n) ? cnt[i] : 0;
    if (i < n) dinv[i] = rsqrtf((float)v + 1.0f);   // + self-loop
    int s = v;
#pragma unroll
    for (int off = 1; off < 32; off <<= 1) {
        int t = __shfl_up_sync(0xffffffffu, s, off);
        if (lane >= off) s += t;
    }
    if (lane == 31) wsum[w] = s;
    __syncthreads();
    if (w == 0) {
        int ws = wsum[lane];
#pragma unroll
        for (int off = 1; off < 32; off <<= 1) {
            int t = __shfl_up_sync(0xffffffffu, ws, off);
            if (lane >= off) ws += t;
        }
        wsum[lane] = ws;
    }
    __syncthreads();
    if (w > 0) s += wsum[w - 1];
    if (i < n) incl[i] = s;
    if (threadIdx.x == SBS - 1) bsum[blockIdx.x] = s;
}

// single-block exclusive scan of block sums
__global__ __launch_bounds__(SBS) void k_scan2(int* bsum, int nb) {
    __shared__ int wsum[32];
    int t = threadIdx.x, lane = t & 31, w = t >> 5;
    int v = (t < nb) ? bsum[t] : 0;
    int s = v;
#pragma unroll
    for (int off = 1; off < 32; off <<= 1) {
        int u = __shfl_up_sync(0xffffffffu, s, off);
        if (lane >= off) s += u;
    }
    if (lane == 31) wsum[w] = s;
    __syncthreads();
    if (w == 0) {
        int ws = wsum[lane];
#pragma unroll
        for (int off = 1; off < 32; off <<= 1) {
            int u = __shfl_up_sync(0xffffffffu, ws, off);
            if (lane >= off) ws += u;
        }
        wsum[lane] = ws;
    }
    __syncthreads();
    if (w > 0) s += wsum[w - 1];
    if (t < nb) bsum[t] = s - v;                    // exclusive
}

__global__ __launch_bounds__(256) void k_scan3(const int* __restrict__ incl,
                                               const int* __restrict__ bsum,
                                               int* rowptr, int n) {
    int i = blockIdx.x * 256 + threadIdx.x;
    if (i < n) rowptr[i + 1] = incl[i] + bsum[i / SBS];
    if (i == 0) rowptr[0] = 0;
}

__global__ __launch_bounds__(256) void k_fill(const int* __restrict__ src,
                                              const int* __restrict__ dst,
                                              const int* __restrict__ rowptr,
                                              const float* __restrict__ dinv,
                                              int* cursor, uint2* edge, int e) {
    int i = blockIdx.x * 256 + threadIdx.x;
    if (i >= e) return;
    int s = __ldg(src + i), d = __ldg(dst + i);
    int pos = __ldg(rowptr + d) + atomicAdd(cursor + d, 1);
    uint2 ed;
    ed.x = (unsigned)s;
    ed.y = __float_as_uint(__ldg(dinv + s) * __ldg(dinv + d));
    edge[pos] = ed;
}

__global__ void k_bn(const float* b0, const float* gg0, const float* be0,
                     const float* m0, const float* v0,
                     const float* b1, const float* gg1, const float* be1,
                     const float* m1, const float* v1,
                     const float* b2, const float* gg2, const float* be2,
                     const float* m2, const float* v2,
                     float* A, float* B) {
    int t = threadIdx.x;
    if (t >= 3 * H) return;
    int l = t >> 6, f = t & 63;
    const float* bs[3] = {b0, b1, b2};
    const float* gs[3] = {gg0, gg1, gg2};
    const float* es[3] = {be0, be1, be2};
    const float* ms[3] = {m0, m1, m2};
    const float* vs[3] = {v0, v1, v2};
    float a = gs[l][f] * rsqrtf(vs[l][f] + BN_EPS);
    A[t] = a;
    B[t] = es[l][f] + (bs[l][f] - ms[l][f]) * a;
}

// ---- layer-0 GEMM: fp32 X, bf16 hi/lo split (3 terms), bf16 output --------
template<int K>
__global__ __launch_bounds__(512) void k_gemm_f32(const float* __restrict__ X,
                                                  const float* __restrict__ W,
                                                  __nv_bfloat16* __restrict__ Y,
                                                  int n) {
    extern __shared__ __align__(16) char smem[];
    constexpr int LD = K + 8;
    __nv_bfloat16* Ah = (__nv_bfloat16*)smem;
    __nv_bfloat16* Al = Ah + 128 * LD;
    __nv_bfloat16* Bh = Al + 128 * LD;
    __nv_bfloat16* Bl = Bh + 64 * LD;

    const int t = threadIdx.x;
    const int wid = t >> 5, lane = t & 31;
    const int row0 = blockIdx.x * 128;

#pragma unroll
    for (int i = 0; i < 128 * (K / 4) / 512; i++) {
        int idx = t + i * 512;
        int r = idx / (K / 4);
        int k0 = (idx % (K / 4)) * 4;
        int gr = row0 + r;
        float4 v = make_float4(0.f, 0.f, 0.f, 0.f);
        if (gr < n) v = *(const float4*)(X + (size_t)gr * K + k0);
        float hx = __bfloat162float(__float2bfloat16(v.x));
        float hy = __bfloat162float(__float2bfloat16(v.y));
        float hz = __bfloat162float(__float2bfloat16(v.z));
        float hw = __bfloat162float(__float2bfloat16(v.w));
        uint2 hp, lp;
        hp.x = pack_bf2(v.x, v.y);
        hp.y = pack_bf2(v.z, v.w);
        lp.x = pack_bf2(v.x - hx, v.y - hy);
        lp.y = pack_bf2(v.z - hz, v.w - hw);
        *(uint2*)&Ah[r * LD + k0] = hp;
        *(uint2*)&Al[r * LD + k0] = lp;
    }
#pragma unroll
    for (int i = 0; i < K * 64 / 512; i++) {
        int idx = t + i * 512;
        int k = idx >> 6, nn = idx & 63;
        float w = W[(size_t)k * 64 + nn];
        float hh = __bfloat162float(__float2bfloat16(w));
        Bh[nn * LD + k] = __float2bfloat16(w);
        Bl[nn * LD + k] = __float2bfloat16(w - hh);
    }
    __syncthreads();

    float c[4][4];
#pragma unroll
    for (int j = 0; j < 4; j++) {
        c[j][0] = 0.f; c[j][1] = 0.f; c[j][2] = 0.f; c[j][3] = 0.f;
    }
    const int m0 = (wid >> 1) * 16;
    const int nb = (wid & 1) * 32;
    const uint32_t sAh = smem_u32(Ah), sAl = smem_u32(Al);
    const uint32_t sBh = smem_u32(Bh), sBl = smem_u32(Bl);
    uint32_t aOff = (uint32_t)(((m0 + (lane & 15)) * LD + ((lane >> 4) << 3)) * 2);
    uint32_t bOff = (uint32_t)(((nb + (lane & 7) + ((lane >> 4) << 3)) * LD
                                + (lane & 8)) * 2);

#pragma unroll
    for (int kc = 0; kc < K / 16; kc++) {
        uint32_t ah[4], al[4];
        ldsm4(ah, sAh + aOff + kc * 32);
        ldsm4(al, sAl + aOff + kc * 32);
#pragma unroll
        for (int j = 0; j < 2; j++) {
            uint32_t off = bOff + (uint32_t)(j * 16 * LD * 2) + kc * 32;
            uint32_t bh[4], bl[4];
            ldsm4(bh, sBh + off);
            ldsm4(bl, sBl + off);
            mma_bf16(c[2 * j],     ah, bh);
            mma_bf16(c[2 * j],     ah, bl);
            mma_bf16(c[2 * j],     al, bh);
            mma_bf16(c[2 * j + 1], ah, bh + 2);
            mma_bf16(c[2 * j + 1], ah, bl + 2);
            mma_bf16(c[2 * j + 1], al, bh + 2);
        }
    }

    int cr = lane >> 2, cc = (lane & 3) * 2;
    int r0g = row0 + m0 + cr;
    int r1g = r0g + 8;
    if (r0g < n) {
#pragma unroll
        for (int jj = 0; jj < 4; jj++)
            *(uint32_t*)(Y + (size_t)r0g * 64 + nb + jj * 8 + cc)
                = pack_bf2(c[jj][0], c[jj][1]);
    }
    if (r1g < n) {
#pragma unroll
        for (int jj = 0; jj < 4; jj++)
            *(uint32_t*)(Y + (size_t)r1g * 64 + nb + jj * 8 + cc)
                = pack_bf2(c[jj][2], c[jj][3]);
    }
}

// ---- layers 1/2 GEMM: bf16 X (exact), B hi/lo split (2 terms) -------------
__global__ __launch_bounds__(512) void k_gemm_bf(const __nv_bfloat16* __restrict__ X,
                                                 const float* __restrict__ W,
                                                 __nv_bfloat16* __restrict__ Y,
                                                 int n) {
    constexpr int K = 64;
    extern __shared__ __align__(16) char smem[];
    constexpr int LD = K + 8;
    __nv_bfloat16* Ah = (__nv_bfloat16*)smem;     // [128][LD]
    __nv_bfloat16* Bh = Ah + 128 * LD;            // [64][LD]
    __nv_bfloat16* Bl = Bh + 64 * LD;

    const int t = threadIdx.x;
    const int wid = t >> 5, lane = t & 31;
    const int row0 = blockIdx.x * 128;

#pragma unroll
    for (int i = 0; i < 4; i++) {
        int idx = t + i * 512;
        int r = idx >> 4;
        int k0 = (idx & 15) * 4;
        int gr = row0 + r;
        uint2 v = make_uint2(0u, 0u);
        if (gr < n) v = *(const uint2*)(X + (size_t)gr * K + k0);
        *(uint2*)&Ah[r * LD + k0] = v;
    }
#pragma unroll
    for (int i = 0; i < K * 64 / 512; i++) {
        int idx = t + i * 512;
        int k = idx >> 6, nn = idx & 63;
        float w = W[(size_t)k * 64 + nn];
        float hh = __bfloat162float(__float2bfloat16(w));
        Bh[nn * LD + k] = __float2bfloat16(w);
        Bl[nn * LD + k] = __float2bfloat16(w - hh);
    }
    __syncthreads();

    float c[4][4];
#pragma unroll
    for (int j = 0; j < 4; j++) {
        c[j][0] = 0.f; c[j][1] = 0.f; c[j][2] = 0.f; c[j][3] = 0.f;
    }
    const int m0 = (wid >> 1) * 16;
    const int nb = (wid & 1) * 32;
    const uint32_t sAh = smem_u32(Ah);
    const uint32_t sBh = smem_u32(Bh), sBl = smem_u32(Bl);
    uint32_t aOff = (uint32_t)(((m0 + (lane & 15)) * LD + ((lane >> 4) << 3)) * 2);
    uint32_t bOff = (uint32_t)(((nb + (lane & 7) + ((lane >> 4) << 3)) * LD
                                + (lane & 8)) * 2);

#pragma unroll
    for (int kc = 0; kc < K / 16; kc++) {
        uint32_t ah[4];
        ldsm4(ah, sAh + aOff + kc * 32);
#pragma unroll
        for (int j = 0; j < 2; j++) {
            uint32_t off = bOff + (uint32_t)(j * 16 * LD * 2) + kc * 32;
            uint32_t bh[4], bl[4];
            ldsm4(bh, sBh + off);
            ldsm4(bl, sBl + off);
            mma_bf16(c[2 * j],     ah, bh);
            mma_bf16(c[2 * j],     ah, bl);
            mma_bf16(c[2 * j + 1], ah, bh + 2);
            mma_bf16(c[2 * j + 1], ah, bl + 2);
        }
    }

    int cr = lane >> 2, cc = (lane & 3) * 2;
    int r0g = row0 + m0 + cr;
    int r1g = r0g + 8;
    if (r0g < n) {
#pragma unroll
        for (int jj = 0; jj < 4; jj++)
            *(uint32_t*)(Y + (size_t)r0g * 64 + nb + jj * 8 + cc)
                = pack_bf2(c[jj][0], c[jj][1]);
    }
    if (r1g < n) {
#pragma unroll
        for (int jj = 0; jj < 4; jj++)
            *(uint32_t*)(Y + (size_t)r1g * 64 + nb + jj * 8 + cc)
                = pack_bf2(c[jj][2], c[jj][3]);
    }
}

// --------- fused gather (bf16 h) + self-loop + BN + ReLU (+pool) -----------
// Round-7 proven form: warp per node, 16 lanes x uint2, 2 edge parities;
// edge stream packed as uint2 {src, weight}.
template<bool POOL>
__global__ __launch_bounds__(256) void k_gather(const int* __restrict__ rowptr,
                                                const uint2* __restrict__ edge,
                                                const float* __restrict__ dinv,
                                                const __nv_bfloat16* __restrict__ h,
                                                __nv_bfloat16* __restrict__ y,
                                                const float* __restrict__ bnA,
                                                const float* __restrict__ bnB,
                                                const int* __restrict__ batch,
                                                float4* pooled, int n) {
    int node = blockIdx.x * 8 + (threadIdx.x >> 5);
    if (node >= n) return;
    int lane = threadIdx.x & 31;
    int c = lane & 15, p = lane >> 4;
    int beg = __ldg(rowptr + node), end = __ldg(rowptr + node + 1);

    float4 acc = make_float4(0.f, 0.f, 0.f, 0.f);
#pragma unroll 2
    for (int j = beg + p; j < end; j += 2) {
        uint2 ew = __ldg(edge + j);
        int s = (int)ew.x;
        float w = __uint_as_float(ew.y);
        uint2 u = __ldg((const uint2*)(h + (size_t)s * 64) + c);
        float2 f0 = __bfloat1622float2(*(__nv_bfloat162*)&u.x);
        float2 f1 = __bfloat1622float2(*(__nv_bfloat162*)&u.y);
        acc.x = fmaf(f0.x, w, acc.x);
        acc.y = fmaf(f0.y, w, acc.y);
        acc.z = fmaf(f1.x, w, acc.z);
        acc.w = fmaf(f1.y, w, acc.w);
    }
    acc.x += __shfl_down_sync(0xffffffffu, acc.x, 16);
    acc.y += __shfl_down_sync(0xffffffffu, acc.y, 16);
    acc.z += __shfl_down_sync(0xffffffffu, acc.z, 16);
    acc.w += __shfl_down_sync(0xffffffffu, acc.w, 16);

    if (p == 0) {
        float di = __ldg(dinv + node);
        float d2 = di * di;
        uint2 u = __ldg((const uint2*)(h + (size_t)node * 64) + c);
        float2 h0 = __bfloat1622float2(*(__nv_bfloat162*)&u.x);
        float2 h1 = __bfloat1622float2(*(__nv_bfloat162*)&u.y);
        float4 A = *(const float4*)(bnA + c * 4);
        float4 B = *(const float4*)(bnB + c * 4);
        float4 o;
        o.x = fmaxf(fmaf(fmaf(h0.x, d2, acc.x), A.x, B.x), 0.f);
        o.y = fmaxf(fmaf(fmaf(h0.y, d2, acc.y), A.y, B.y), 0.f);
        o.z = fmaxf(fmaf(fmaf(h1.x, d2, acc.z), A.z, B.z), 0.f);
        o.w = fmaxf(fmaf(fmaf(h1.y, d2, acc.w), A.w, B.w), 0.f);
        uint2 ob;
        ob.x = pack_bf2(o.x, o.y);
        ob.y = pack_bf2(o.z, o.w);
        ((uint2*)(y + (size_t)node * 64))[c] = ob;
        if (POOL)
            red_add_v4(pooled + (size_t)__ldg(batch + node) * HV + c, o);
    }
}

// ---------------- readout MLP ----------------
__global__ __launch_bounds__(256) void k_mlp(const float* __restrict__ pooled,
                                             const float* __restrict__ l1w,
                                             const float* __restrict__ l1b,
                                             const float* __restrict__ l2w,
                                             const float* __restrict__ l2b,
                                             float* __restrict__ out, int g) {
    __shared__ float4 W1[64 * 8];
    __shared__ float  B1[32];
    __shared__ float  W2[64];
    __shared__ float  B2[2];
    int t = threadIdx.x;
    for (int idx = t; idx < 512; idx += 256) W1[idx] = ((const float4*)l1w)[idx];
    if (t < 32) B1[t] = l1b[t];
    if (t < 64) W2[t] = l2w[t];
    if (t < 2)  B2[t] = l2b[t];
    __syncthreads();

    int gi = blockIdx.x * 256 + t;
    if (gi >= g) return;

    float hid[32];
#pragma unroll
    for (int j = 0; j < 32; j++) hid[j] = B1[j];
    for (int k = 0; k < 64; k++) {
        float p = pooled[(size_t)gi * 64 + k];
#pragma unroll
        for (int jj = 0; jj < 8; jj++) {
            float4 w = W1[k * 8 + jj];
            hid[jj * 4 + 0] = fmaf(p, w.x, hid[jj * 4 + 0]);
            hid[jj * 4 + 1] = fmaf(p, w.y, hid[jj * 4 + 1]);
            hid[jj * 4 + 2] = fmaf(p, w.z, hid[jj * 4 + 2]);
            hid[jj * 4 + 3] = fmaf(p, w.w, hid[jj * 4 + 3]);
        }
    }
    float o0 = B2[0], o1 = B2[1];
#pragma unroll
    for (int j = 0; j < 32; j++) {
        float hj = fmaxf(hid[j], 0.f);
        o0 = fmaf(hj, W2[j * 2 + 0], o0);
        o1 = fmaf(hj, W2[j * 2 + 1], o1);
    }
    out[(size_t)gi * 2 + 0] = o0;
    out[(size_t)gi * 2 + 1] = o1;
}

// ---------------- launch ----------------
extern "C" void kernel_launch(void* const* d_in, const int* in_sizes, int n_in,
                              void* d_out, int out_size) {
    const float* x     = (const float*)d_in[0];
    const int*   ei    = (const int*)  d_in[1];
    const int*   batch = (const int*)  d_in[2];
    const float* w0 = (const float*)d_in[3];
    const float* b0 = (const float*)d_in[4];
    const float* w1 = (const float*)d_in[5];
    const float* b1 = (const float*)d_in[6];
    const float* w2 = (const float*)d_in[7];
    const float* b2 = (const float*)d_in[8];
    const float* gg0 = (const float*)d_in[9],  *be0 = (const float*)d_in[10];
    const float* m0  = (const float*)d_in[11], *v0  = (const float*)d_in[12];
    const float* gg1 = (const float*)d_in[13], *be1 = (const float*)d_in[14];
    const float* m1  = (const float*)d_in[15], *v1  = (const float*)d_in[16];
    const float* gg2 = (const float*)d_in[17], *be2 = (const float*)d_in[18];
    const float* m2  = (const float*)d_in[19], *v2  = (const float*)d_in[20];
    const float* l1w = (const float*)d_in[21], *l1b = (const float*)d_in[22];
    const float* l2w = (const float*)d_in[23], *l2b = (const float*)d_in[24];

    const int n = in_sizes[0] / F_IN;
    const int e = in_sizes[1] / 2;
    const int g = out_size / 2;
    if (n <= 0) return;

    __nv_bfloat16 *bufA, *bufB;
    float4 *pooled;
    float  *dinv, *bnA, *bnB;
    int    *degcnt, *cursor, *incl, *bsum, *rowptr;
    uint2  *edge;
    cudaGetSymbolAddress((void**)&bufA,   g_bufA);
    cudaGetSymbolAddress((void**)&bufB,   g_bufB);
    cudaGetSymbolAddress((void**)&pooled, g_pooled);
    cudaGetSymbolAddress((void**)&dinv,   g_dinv);
    cudaGetSymbolAddress((void**)&degcnt, g_degcnt);
    cudaGetSymbolAddress((void**)&cursor, g_cursor);
    cudaGetSymbolAddress((void**)&incl,   g_incl);
    cudaGetSymbolAddress((void**)&bsum,   g_bsum);
    cudaGetSymbolAddress((void**)&rowptr, g_rowptr);
    cudaGetSymbolAddress((void**)&edge,   g_edge);
    cudaGetSymbolAddress((void**)&bnA,    g_bnA);
    cudaGetSymbolAddress((void**)&bnB,    g_bnB);

    const int* src = ei;
    const int* dst = ei + e;

    const int TB = 256;
    const int gInit = (((n > g * HV) ? n : g * HV) + TB - 1) / TB;
    const int gEdge = (e + TB - 1) / TB;
    const int gNode = (n + TB - 1) / TB;
    const int nbScan = (n + SBS - 1) / SBS;
    const int gGemm = (n + 127) / 128;
    const int gGath = (n + 7) / 8;

    const int SM128 = (128 * (F_IN + 8) * 2 + 64 * (F_IN + 8) * 2) * 2; // 104448
    const int SMBF  = (128 * (H + 8) + 2 * 64 * (H + 8)) * 2;           // 36864
    cudaFuncSetAttribute(k_gemm_f32<F_IN>,
                         cudaFuncAttributeMaxDynamicSharedMemorySize, SM128);
    cudaFuncSetAttribute(k_gemm_bf,
                         cudaFuncAttributeMaxDynamicSharedMemorySize, SMBF);

    static cudaStream_t s_pre = nullptr;
    static cudaEvent_t ev_fork = nullptr, ev_join = nullptr;
    if (s_pre == nullptr) {
        cudaStreamCreateWithFlags(&s_pre, cudaStreamNonBlocking);
        cudaEventCreateWithFlags(&ev_fork, cudaEventDisableTiming);
        cudaEventCreateWithFlags(&ev_join, cudaEventDisableTiming);
    }

    // ---- fork: graph preprocessing concurrent with gemm0 ----
    cudaEventRecord(ev_fork, 0);
    cudaStreamWaitEvent(s_pre, ev_fork, 0);
    k_init <<<gInit, TB, 0, s_pre>>>(pooled, degcnt, cursor, n, g);
    k_hist <<<gEdge, TB, 0, s_pre>>>(dst, degcnt, e);
    k_scan1<<<nbScan, SBS, 0, s_pre>>>(degcnt, incl, bsum, dinv, n);
    k_scan2<<<1, SBS, 0, s_pre>>>(bsum, nbScan);
    k_scan3<<<gNode, TB, 0, s_pre>>>(incl, bsum, rowptr, n);
    k_fill <<<gEdge, TB, 0, s_pre>>>(src, dst, rowptr, dinv, cursor, edge, e);
    cudaEventRecord(ev_join, s_pre);

    k_bn<<<1, 3 * H>>>(b0, gg0, be0, m0, v0, b1, gg1, be1, m1, v1,
                       b2, gg2, be2, m2, v2, bnA, bnB);
    k_gemm_f32<F_IN><<<gGemm, 512, SM128>>>(x, w0, bufA, n);

    cudaStreamWaitEvent(0, ev_join, 0);

    // ----- layer 0 gather -----
    k_gather<false><<<gGath, TB>>>(rowptr, edge, dinv, bufA, bufB,
                                   bnA, bnB, batch, pooled, n);
    // ----- layer 1 -----
    k_gemm_bf<<<gGemm, 512, SMBF>>>(bufB, w1, bufA, n);
    k_gather<false><<<gGath, TB>>>(rowptr, edge, dinv, bufA, bufB,
                                   bnA + H, bnB + H, batch, pooled, n);
    // ----- layer 2 (pool fused) -----
    k_gemm_bf<<<gGemm, 512, SMBF>>>(bufB, w2, bufA, n);
    k_gather<true><<<gGath, TB>>>(rowptr, edge, dinv, bufA, bufB,
                                  bnA + 2 * H, bnB + 2 * H, batch, pooled, n);

    // ----- readout MLP -----
    k_mlp<<<(g + TB - 1) / TB, TB>>>((const float*)pooled, l1w, l1b, l2w, l2b,
                                     (float*)d_out, g);
}

// round 12
// speedup vs baseline: 1.1651x; 1.0056x over previous
#include <cuda_runtime.h>
#include <cuda_bf16.h>
#include <math.h>
#include <stdint.h>

#define F_IN   128
#define H      64
#define HV     16
#define N_MAX  100000
#define E_MAX  1800000            // 1.6M edges + up to 100k pad slots
#define G_MAX  4096
#define BN_EPS 1e-5f
#define SBS    1024

// ---------------- scratch (device globals: allocation-free) ----------------
__device__ __nv_bfloat16 g_bufA[(size_t)N_MAX * H];   // bf16 activations
__device__ __nv_bfloat16 g_bufB[(size_t)N_MAX * H];
__device__ float4 g_pooled[(size_t)G_MAX * HV];
__device__ float  g_dinv[N_MAX];
__device__ int    g_degcnt[N_MAX];
__device__ int    g_cursor[N_MAX];
__device__ int    g_incl[N_MAX];
__device__ int    g_bsum[SBS];
__device__ int    g_rowptr[N_MAX + 1];
__device__ uint2  g_edge[E_MAX];          // packed {src, weight}
__device__ float  g_bnA[3 * H];
__device__ float  g_bnB[3 * H];

// ---------------- helpers ----------------
__device__ __forceinline__ uint32_t smem_u32(const void* p) {
    uint32_t a;
    asm("{ .reg .u64 t; cvta.to.shared.u64 t, %1; cvt.u32.u64 %0, t; }"
        : "=r"(a) : "l"(p));
    return a;
}
__device__ __forceinline__ void red_add_v4(float4* p, float4 v) {
    asm volatile("red.global.add.v4.f32 [%0], {%1, %2, %3, %4};"
                 :: "l"(p), "f"(v.x), "f"(v.y), "f"(v.z), "f"(v.w)
                 : "memory");
}
__device__ __forceinline__ void ldsm4(uint32_t* r, uint32_t addr) {
    asm volatile("ldmatrix.sync.aligned.m8n8.x4.shared.b16 {%0,%1,%2,%3}, [%4];"
                 : "=r"(r[0]), "=r"(r[1]), "=r"(r[2]), "=r"(r[3]) : "r"(addr));
}
__device__ __forceinline__ void mma_bf16(float* c, const uint32_t* a,
                                         const uint32_t* b) {
    asm volatile(
        "mma.sync.aligned.m16n8k16.row.col.f32.bf16.bf16.f32 "
        "{%0,%1,%2,%3}, {%4,%5,%6,%7}, {%8,%9}, {%0,%1,%2,%3};"
        : "+f"(c[0]), "+f"(c[1]), "+f"(c[2]), "+f"(c[3])
        : "r"(a[0]), "r"(a[1]), "r"(a[2]), "r"(a[3]), "r"(b[0]), "r"(b[1]));
}
__device__ __forceinline__ uint32_t pack_bf2(float lo, float hi) {
    __nv_bfloat162 r = __floats2bfloat162_rn(lo, hi);
    return *(uint32_t*)&r;
}

// ---------------- setup kernels ----------------
__global__ __launch_bounds__(256) void k_init(float4* pooled, int* degcnt,
                                              int* cursor, int n, int g) {
    int i = blockIdx.x * 256 + threadIdx.x;
    if (i < g * HV) pooled[i] = make_float4(0.f, 0.f, 0.f, 0.f);
    if (i < n) { degcnt[i] = 0; cursor[i] = 0; }
}

__global__ __launch_bounds__(256) void k_hist(const int* __restrict__ dst,
                                              int* degcnt, int e) {
    int i = blockIdx.x * 256 + threadIdx.x;
    if (i < e) atomicAdd(degcnt + __ldg(dst + i), 1);
}

// warp-shuffle inclusive scan of EVEN-PADDED degrees per block; sums to bsum
__global__ __launch_bounds__(SBS) void k_scan1(const int* __restrict__ cnt,
                                               int* incl, int* bsum,
                                               float* dinv, int n) {
    __shared__ int wsum[32];
    int i = blockIdx.x * SBS + threadIdx.x;
    int lane = threadIdx.x & 31, w = threadIdx.x >> 5;
    int v = (i < n) ? cnt[i] : 0;
    if (i < n) dinv[i] = rsqrtf((float)v + 1.0f);   // + self-loop
    int s = (v + 1) & ~1;                           // pad rows to even length
#pragma unroll
    for (int off = 1; off < 32; off <<= 1) {
        int t = __shfl_up_sync(0xffffffffu, s, off);
        if (lane >= off) s += t;
    }
    if (lane == 31) wsum[w] = s;
    __syncthreads();
    if (w == 0) {
        int ws = wsum[lane];
#pragma unroll
        for (int off = 1; off < 32; off <<= 1) {
            int t = __shfl_up_sync(0xffffffffu, ws, off);
            if (lane >= off) ws += t;
        }
        wsum[lane] = ws;
    }
    __syncthreads();
    if (w > 0) s += wsum[w - 1];
    if (i < n) incl[i] = s;
    if (threadIdx.x == SBS - 1) bsum[blockIdx.x] = s;
}

// fused scan2+scan3: each block sums its bsum prefix in-kernel, writes rowptr,
// and zeroes the pad slot of odd-degree rows (exact no-op edge {0, 0.0f}).
__global__ __launch_bounds__(256) void k_scan23(const int* __restrict__ incl,
                                                const int* __restrict__ bsum,
                                                const int* __restrict__ degcnt,
                                                int* rowptr, uint2* edge, int n) {
    __shared__ int red[8];
    __shared__ int pref;
    int t = threadIdx.x;
    int blk = (int)(((size_t)blockIdx.x * 256) / SBS);  // same for whole block
    int part = 0;
    for (int k = t; k < blk; k += 256) part += __ldg(bsum + k);
#pragma unroll
    for (int off = 16; off; off >>= 1)
        part += __shfl_down_sync(0xffffffffu, part, off);
    if ((t & 31) == 0) red[t >> 5] = part;
    __syncthreads();
    if (t == 0) {
        int s = 0;
#pragma unroll
        for (int w = 0; w < 8; w++) s += red[w];
        pref = s;
    }
    __syncthreads();
    int i = blockIdx.x * 256 + t;
    if (i < n) {
        int rp = incl[i] + pref;
        rowptr[i + 1] = rp;
        if (__ldg(degcnt + i) & 1) edge[rp - 1] = make_uint2(0u, 0u);
    }
    if (i == 0) rowptr[0] = 0;
}

__global__ __launch_bounds__(256) void k_fill(const int* __restrict__ src,
                                              const int* __restrict__ dst,
                                              const int* __restrict__ rowptr,
                                              const float* __restrict__ dinv,
                                              int* cursor, uint2* edge, int e) {
    int i = blockIdx.x * 256 + threadIdx.x;
    if (i >= e) return;
    int s = __ldg(src + i), d = __ldg(dst + i);
    int pos = __ldg(rowptr + d) + atomicAdd(cursor + d, 1);
    uint2 ed;
    ed.x = (unsigned)s;
    ed.y = __float_as_uint(__ldg(dinv + s) * __ldg(dinv + d));
    edge[pos] = ed;
}

__global__ void k_bn(const float* b0, const float* gg0, const float* be0,
                     const float* m0, const float* v0,
                     const float* b1, const float* gg1, const float* be1,
                     const float* m1, const float* v1,
                     const float* b2, const float* gg2, const float* be2,
                     const float* m2, const float* v2,
                     float* A, float* B) {
    int t = threadIdx.x;
    if (t >= 3 * H) return;
    int l = t >> 6, f = t & 63;
    const float* bs[3] = {b0, b1, b2};
    const float* gs[3] = {gg0, gg1, gg2};
    const float* es[3] = {be0, be1, be2};
    const float* ms[3] = {m0, m1, m2};
    const float* vs[3] = {v0, v1, v2};
    float a = gs[l][f] * rsqrtf(vs[l][f] + BN_EPS);
    A[t] = a;
    B[t] = es[l][f] + (bs[l][f] - ms[l][f]) * a;
}

// ---- layer-0 GEMM: fp32 X, bf16 hi/lo split (3 terms), bf16 output --------
template<int K>
__global__ __launch_bounds__(512) void k_gemm_f32(const float* __restrict__ X,
                                                  const float* __restrict__ W,
                                                  __nv_bfloat16* __restrict__ Y,
                                                  int n) {
    extern __shared__ __align__(16) char smem[];
    constexpr int LD = K + 8;
    __nv_bfloat16* Ah = (__nv_bfloat16*)smem;
    __nv_bfloat16* Al = Ah + 128 * LD;
    __nv_bfloat16* Bh = Al + 128 * LD;
    __nv_bfloat16* Bl = Bh + 64 * LD;

    const int t = threadIdx.x;
    const int wid = t >> 5, lane = t & 31;
    const int row0 = blockIdx.x * 128;

#pragma unroll
    for (int i = 0; i < 128 * (K / 4) / 512; i++) {
        int idx = t + i * 512;
        int r = idx / (K / 4);
        int k0 = (idx % (K / 4)) * 4;
        int gr = row0 + r;
        float4 v = make_float4(0.f, 0.f, 0.f, 0.f);
        if (gr < n) v = *(const float4*)(X + (size_t)gr * K + k0);
        float hx = __bfloat162float(__float2bfloat16(v.x));
        float hy = __bfloat162float(__float2bfloat16(v.y));
        float hz = __bfloat162float(__float2bfloat16(v.z));
        float hw = __bfloat162float(__float2bfloat16(v.w));
        uint2 hp, lp;
        hp.x = pack_bf2(v.x, v.y);
        hp.y = pack_bf2(v.z, v.w);
        lp.x = pack_bf2(v.x - hx, v.y - hy);
        lp.y = pack_bf2(v.z - hz, v.w - hw);
        *(uint2*)&Ah[r * LD + k0] = hp;
        *(uint2*)&Al[r * LD + k0] = lp;
    }
#pragma unroll
    for (int i = 0; i < K * 64 / 512; i++) {
        int idx = t + i * 512;
        int k = idx >> 6, nn = idx & 63;
        float w = W[(size_t)k * 64 + nn];
        float hh = __bfloat162float(__float2bfloat16(w));
        Bh[nn * LD + k] = __float2bfloat16(w);
        Bl[nn * LD + k] = __float2bfloat16(w - hh);
    }
    __syncthreads();

    float c[4][4];
#pragma unroll
    for (int j = 0; j < 4; j++) {
        c[j][0] = 0.f; c[j][1] = 0.f; c[j][2] = 0.f; c[j][3] = 0.f;
    }
    const int m0 = (wid >> 1) * 16;
    const int nb = (wid & 1) * 32;
    const uint32_t sAh = smem_u32(Ah), sAl = smem_u32(Al);
    const uint32_t sBh = smem_u32(Bh), sBl = smem_u32(Bl);
    uint32_t aOff = (uint32_t)(((m0 + (lane & 15)) * LD + ((lane >> 4) << 3)) * 2);
    uint32_t bOff = (uint32_t)(((nb + (lane & 7) + ((lane >> 4) << 3)) * LD
                                + (lane & 8)) * 2);

#pragma unroll
    for (int kc = 0; kc < K / 16; kc++) {
        uint32_t ah[4], al[4];
        ldsm4(ah, sAh + aOff + kc * 32);
        ldsm4(al, sAl + aOff + kc * 32);
#pragma unroll
        for (int j = 0; j < 2; j++) {
            uint32_t off = bOff + (uint32_t)(j * 16 * LD * 2) + kc * 32;
            uint32_t bh[4], bl[4];
            ldsm4(bh, sBh + off);
            ldsm4(bl, sBl + off);
            mma_bf16(c[2 * j],     ah, bh);
            mma_bf16(c[2 * j],     ah, bl);
            mma_bf16(c[2 * j],     al, bh);
            mma_bf16(c[2 * j + 1], ah, bh + 2);
            mma_bf16(c[2 * j + 1], ah, bl + 2);
            mma_bf16(c[2 * j + 1], al, bh + 2);
        }
    }

    int cr = lane >> 2, cc = (lane & 3) * 2;
    int r0g = row0 + m0 + cr;
    int r1g = r0g + 8;
    if (r0g < n) {
#pragma unroll
        for (int jj = 0; jj < 4; jj++)
            *(uint32_t*)(Y + (size_t)r0g * 64 + nb + jj * 8 + cc)
                = pack_bf2(c[jj][0], c[jj][1]);
    }
    if (r1g < n) {
#pragma unroll
        for (int jj = 0; jj < 4; jj++)
            *(uint32_t*)(Y + (size_t)r1g * 64 + nb + jj * 8 + cc)
                = pack_bf2(c[jj][2], c[jj][3]);
    }
}

// ---- layers 1/2 GEMM: bf16 X (exact), B hi/lo split (2 terms) -------------
__global__ __launch_bounds__(512) void k_gemm_bf(const __nv_bfloat16* __restrict__ X,
                                                 const float* __restrict__ W,
                                                 __nv_bfloat16* __restrict__ Y,
                                                 int n) {
    constexpr int K = 64;
    extern __shared__ __align__(16) char smem[];
    constexpr int LD = K + 8;
    __nv_bfloat16* Ah = (__nv_bfloat16*)smem;     // [128][LD]
    __nv_bfloat16* Bh = Ah + 128 * LD;            // [64][LD]
    __nv_bfloat16* Bl = Bh + 64 * LD;

    const int t = threadIdx.x;
    const int wid = t >> 5, lane = t & 31;
    const int row0 = blockIdx.x * 128;

#pragma unroll
    for (int i = 0; i < 4; i++) {
        int idx = t + i * 512;
        int r = idx >> 4;
        int k0 = (idx & 15) * 4;
        int gr = row0 + r;
        uint2 v = make_uint2(0u, 0u);
        if (gr < n) v = *(const uint2*)(X + (size_t)gr * K + k0);
        *(uint2*)&Ah[r * LD + k0] = v;
    }
#pragma unroll
    for (int i = 0; i < K * 64 / 512; i++) {
        int idx = t + i * 512;
        int k = idx >> 6, nn = idx & 63;
        float w = W[(size_t)k * 64 + nn];
        float hh = __bfloat162float(__float2bfloat16(w));
        Bh[nn * LD + k] = __float2bfloat16(w);
        Bl[nn * LD + k] = __float2bfloat16(w - hh);
    }
    __syncthreads();

    float c[4][4];
#pragma unroll
    for (int j = 0; j < 4; j++) {
        c[j][0] = 0.f; c[j][1] = 0.f; c[j][2] = 0.f; c[j][3] = 0.f;
    }
    const int m0 = (wid >> 1) * 16;
    const int nb = (wid & 1) * 32;
    const uint32_t sAh = smem_u32(Ah);
    const uint32_t sBh = smem_u32(Bh), sBl = smem_u32(Bl);
    uint32_t aOff = (uint32_t)(((m0 + (lane & 15)) * LD + ((lane >> 4) << 3)) * 2);
    uint32_t bOff = (uint32_t)(((nb + (lane & 7) + ((lane >> 4) << 3)) * LD
                                + (lane & 8)) * 2);

#pragma unroll
    for (int kc = 0; kc < K / 16; kc++) {
        uint32_t ah[4];
        ldsm4(ah, sAh + aOff + kc * 32);
#pragma unroll
        for (int j = 0; j < 2; j++) {
            uint32_t off = bOff + (uint32_t)(j * 16 * LD * 2) + kc * 32;
            uint32_t bh[4], bl[4];
            ldsm4(bh, sBh + off);
            ldsm4(bl, sBl + off);
            mma_bf16(c[2 * j],     ah, bh);
            mma_bf16(c[2 * j],     ah, bl);
            mma_bf16(c[2 * j + 1], ah, bh + 2);
            mma_bf16(c[2 * j + 1], ah, bl + 2);
        }
    }

    int cr = lane >> 2, cc = (lane & 3) * 2;
    int r0g = row0 + m0 + cr;
    int r1g = r0g + 8;
    if (r0g < n) {
#pragma unroll
        for (int jj = 0; jj < 4; jj++)
            *(uint32_t*)(Y + (size_t)r0g * 64 + nb + jj * 8 + cc)
                = pack_bf2(c[jj][0], c[jj][1]);
    }
    if (r1g < n) {
#pragma unroll
        for (int jj = 0; jj < 4; jj++)
            *(uint32_t*)(Y + (size_t)r1g * 64 + nb + jj * 8 + cc)
                = pack_bf2(c[jj][2], c[jj][3]);
    }
}

// --------- fused gather (bf16 h) + self-loop + BN + ReLU (+pool) -----------
// Warp per node, 16 lanes x uint2, 2 parities; rows even-padded so both
// parities run identical trip counts; edge record software-pipelined so the
// h-load never waits on the edge-load of the same iteration.
template<bool POOL>
__global__ __launch_bounds__(256) void k_gather(const int* __restrict__ rowptr,
                                                const uint2* __restrict__ edge,
                                                const float* __restrict__ dinv,
                                                const __nv_bfloat16* __restrict__ h,
                                                __nv_bfloat16* __restrict__ y,
                                                const float* __restrict__ bnA,
                                                const float* __restrict__ bnB,
                                                const int* __restrict__ batch,
                                                float4* pooled, int n) {
    int node = blockIdx.x * 8 + (threadIdx.x >> 5);
    if (node >= n) return;
    int lane = threadIdx.x & 31;
    int c = lane & 15, p = lane >> 4;
    int beg = __ldg(rowptr + node), end = __ldg(rowptr + node + 1);

    float4 acc = make_float4(0.f, 0.f, 0.f, 0.f);
    int j = beg + p;
    if (j < end) {
        uint2 ew = __ldg(edge + j);
#pragma unroll 2
        for (; j + 2 < end; j += 2) {
            uint2 ewn = __ldg(edge + j + 2);       // prefetch next record
            int s = (int)ew.x;
            float w = __uint_as_float(ew.y);
            uint2 u = __ldg((const uint2*)(h + (size_t)s * 64) + c);
            float2 f0 = __bfloat1622float2(*(__nv_bfloat162*)&u.x);
            float2 f1 = __bfloat1622float2(*(__nv_bfloat162*)&u.y);
            acc.x = fmaf(f0.x, w, acc.x);
            acc.y = fmaf(f0.y, w, acc.y);
            acc.z = fmaf(f1.x, w, acc.z);
            acc.w = fmaf(f1.y, w, acc.w);
            ew = ewn;
        }
        {   // final edge of this parity
            int s = (int)ew.x;
            float w = __uint_as_float(ew.y);
            uint2 u = __ldg((const uint2*)(h + (size_t)s * 64) + c);
            float2 f0 = __bfloat1622float2(*(__nv_bfloat162*)&u.x);
            float2 f1 = __bfloat1622float2(*(__nv_bfloat162*)&u.y);
            acc.x = fmaf(f0.x, w, acc.x);
            acc.y = fmaf(f0.y, w, acc.y);
            acc.z = fmaf(f1.x, w, acc.z);
            acc.w = fmaf(f1.y, w, acc.w);
        }
    }
    acc.x += __shfl_down_sync(0xffffffffu, acc.x, 16);
    acc.y += __shfl_down_sync(0xffffffffu, acc.y, 16);
    acc.z += __shfl_down_sync(0xffffffffu, acc.z, 16);
    acc.w += __shfl_down_sync(0xffffffffu, acc.w, 16);

    if (p == 0) {
        float di = __ldg(dinv + node);
        float d2 = di * di;
        uint2 u = __ldg((const uint2*)(h + (size_t)node * 64) + c);
        float2 h0 = __bfloat1622float2(*(__nv_bfloat162*)&u.x);
        float2 h1 = __bfloat1622float2(*(__nv_bfloat162*)&u.y);
        float4 A = *(const float4*)(bnA + c * 4);
        float4 B = *(const float4*)(bnB + c * 4);
        float4 o;
        o.x = fmaxf(fmaf(fmaf(h0.x, d2, acc.x), A.x, B.x), 0.f);
        o.y = fmaxf(fmaf(fmaf(h0.y, d2, acc.y), A.y, B.y), 0.f);
        o.z = fmaxf(fmaf(fmaf(h1.x, d2, acc.z), A.z, B.z), 0.f);
        o.w = fmaxf(fmaf(fmaf(h1.y, d2, acc.w), A.w, B.w), 0.f);
        uint2 ob;
        ob.x = pack_bf2(o.x, o.y);
        ob.y = pack_bf2(o.z, o.w);
        ((uint2*)(y + (size_t)node * 64))[c] = ob;
        if (POOL)
            red_add_v4(pooled + (size_t)__ldg(batch + node) * HV + c, o);
    }
}

// ---------------- readout MLP ----------------
__global__ __launch_bounds__(256) void k_mlp(const float* __restrict__ pooled,
                                             const float* __restrict__ l1w,
                                             const float* __restrict__ l1b,
                                             const float* __restrict__ l2w,
                                             const float* __restrict__ l2b,
                                             float* __restrict__ out, int g) {
    __shared__ float4 W1[64 * 8];
    __shared__ float  B1[32];
    __shared__ float  W2[64];
    __shared__ float  B2[2];
    int t = threadIdx.x;
    for (int idx = t; idx < 512; idx += 256) W1[idx] = ((const float4*)l1w)[idx];
    if (t < 32) B1[t] = l1b[t];
    if (t < 64) W2[t] = l2w[t];
    if (t < 2)  B2[t] = l2b[t];
    __syncthreads();

    int gi = blockIdx.x * 256 + t;
    if (gi >= g) return;

    float hid[32];
#pragma unroll
    for (int j = 0; j < 32; j++) hid[j] = B1[j];
    for (int k = 0; k < 64; k++) {
        float p = pooled[(size_t)gi * 64 + k];
#pragma unroll
        for (int jj = 0; jj < 8; jj++) {
            float4 w = W1[k * 8 + jj];
            hid[jj * 4 + 0] = fmaf(p, w.x, hid[jj * 4 + 0]);
            hid[jj * 4 + 1] = fmaf(p, w.y, hid[jj * 4 + 1]);
            hid[jj * 4 + 2] = fmaf(p, w.z, hid[jj * 4 + 2]);
            hid[jj * 4 + 3] = fmaf(p, w.w, hid[jj * 4 + 3]);
        }
    }
    float o0 = B2[0], o1 = B2[1];
#pragma unroll
    for (int j = 0; j < 32; j++) {
        float hj = fmaxf(hid[j], 0.f);
        o0 = fmaf(hj, W2[j * 2 + 0], o0);
        o1 = fmaf(hj, W2[j * 2 + 1], o1);
    }
    out[(size_t)gi * 2 + 0] = o0;
    out[(size_t)gi * 2 + 1] = o1;
}

// ---------------- launch ----------------
extern "C" void kernel_launch(void* const* d_in, const int* in_sizes, int n_in,
                              void* d_out, int out_size) {
    const float* x     = (const float*)d_in[0];
    const int*   ei    = (const int*)  d_in[1];
    const int*   batch = (const int*)  d_in[2];
    const float* w0 = (const float*)d_in[3];
    const float* b0 = (const float*)d_in[4];
    const float* w1 = (const float*)d_in[5];
    const float* b1 = (const float*)d_in[6];
    const float* w2 = (const float*)d_in[7];
    const float* b2 = (const float*)d_in[8];
    const float* gg0 = (const float*)d_in[9],  *be0 = (const float*)d_in[10];
    const float* m0  = (const float*)d_in[11], *v0  = (const float*)d_in[12];
    const float* gg1 = (const float*)d_in[13], *be1 = (const float*)d_in[14];
    const float* m1  = (const float*)d_in[15], *v1  = (const float*)d_in[16];
    const float* gg2 = (const float*)d_in[17], *be2 = (const float*)d_in[18];
    const float* m2  = (const float*)d_in[19], *v2  = (const float*)d_in[20];
    const float* l1w = (const float*)d_in[21], *l1b = (const float*)d_in[22];
    const float* l2w = (const float*)d_in[23], *l2b = (const float*)d_in[24];

    const int n = in_sizes[0] / F_IN;
    const int e = in_sizes[1] / 2;
    const int g = out_size / 2;
    if (n <= 0) return;

    __nv_bfloat16 *bufA, *bufB;
    float4 *pooled;
    float  *dinv, *bnA, *bnB;
    int    *degcnt, *cursor, *incl, *bsum, *rowptr;
    uint2  *edge;
    cudaGetSymbolAddress((void**)&bufA,   g_bufA);
    cudaGetSymbolAddress((void**)&bufB,   g_bufB);
    cudaGetSymbolAddress((void**)&pooled, g_pooled);
    cudaGetSymbolAddress((void**)&dinv,   g_dinv);
    cudaGetSymbolAddress((void**)&degcnt, g_degcnt);
    cudaGetSymbolAddress((void**)&cursor, g_cursor);
    cudaGetSymbolAddress((void**)&incl,   g_incl);
    cudaGetSymbolAddress((void**)&bsum,   g_bsum);
    cudaGetSymbolAddress((void**)&rowptr, g_rowptr);
    cudaGetSymbolAddress((void**)&edge,   g_edge);
    cudaGetSymbolAddress((void**)&bnA,    g_bnA);
    cudaGetSymbolAddress((void**)&bnB,    g_bnB);

    const int* src = ei;
    const int* dst = ei + e;

    const int TB = 256;
    const int gInit = (((n > g * HV) ? n : g * HV) + TB - 1) / TB;
    const int gEdge = (e + TB - 1) / TB;
    const int gNode = (n + TB - 1) / TB;
    const int nbScan = (n + SBS - 1) / SBS;
    const int gGemm = (n + 127) / 128;
    const int gGath = (n + 7) / 8;

    const int SM128 = (128 * (F_IN + 8) * 2 + 64 * (F_IN + 8) * 2) * 2; // 104448
    const int SMBF  = (128 * (H + 8) + 2 * 64 * (H + 8)) * 2;           // 36864
    cudaFuncSetAttribute(k_gemm_f32<F_IN>,
                         cudaFuncAttributeMaxDynamicSharedMemorySize, SM128);
    cudaFuncSetAttribute(k_gemm_bf,
                         cudaFuncAttributeMaxDynamicSharedMemorySize, SMBF);

    static cudaStream_t s_pre = nullptr;
    static cudaEvent_t ev_fork = nullptr, ev_join = nullptr;
    if (s_pre == nullptr) {
        cudaStreamCreateWithFlags(&s_pre, cudaStreamNonBlocking);
        cudaEventCreateWithFlags(&ev_fork, cudaEventDisableTiming);
        cudaEventCreateWithFlags(&ev_join, cudaEventDisableTiming);
    }

    // ---- fork: graph preprocessing concurrent with gemm0 ----
    cudaEventRecord(ev_fork, 0);
    cudaStreamWaitEvent(s_pre, ev_fork, 0);
    k_init  <<<gInit, TB, 0, s_pre>>>(pooled, degcnt, cursor, n, g);
    k_hist  <<<gEdge, TB, 0, s_pre>>>(dst, degcnt, e);
    k_scan1 <<<nbScan, SBS, 0, s_pre>>>(degcnt, incl, bsum, dinv, n);
    k_scan23<<<gNode, TB, 0, s_pre>>>(incl, bsum, degcnt, rowptr, edge, n);
    k_fill  <<<gEdge, TB, 0, s_pre>>>(src, dst, rowptr, dinv, cursor, edge, e);
    cudaEventRecord(ev_join, s_pre);

    k_bn<<<1, 3 * H>>>(b0, gg0, be0, m0, v0, b1, gg1, be1, m1, v1,
                       b2, gg2, be2, m2, v2, bnA, bnB);
    k_gemm_f32<F_IN><<<gGemm, 512, SM128>>>(x, w0, bufA, n);

    cudaStreamWaitEvent(0, ev_join, 0);

    // ----- layer 0 gather -----
    k_gather<false><<<gGath, TB>>>(rowptr, edge, dinv, bufA, bufB,
                                   bnA, bnB, batch, pooled, n);
    // ----- layer 1 -----
    k_gemm_bf<<<gGemm, 512, SMBF>>>(bufB, w1, bufA, n);
    k_gather<false><<<gGath, TB>>>(rowptr, edge, dinv, bufA, bufB,
                                   bnA + H, bnB + H, batch, pooled, n);
    // ----- layer 2 (pool fused) -----
    k_gemm_bf<<<gGemm, 512, SMBF>>>(bufB, w2, bufA, n);
    k_gather<true><<<gGath, TB>>>(rowptr, edge, dinv, bufA, bufB,
                                  bnA + 2 * H, bnB + 2 * H, batch, pooled, n);

    // ----- readout MLP -----
    k_mlp<<<(g + TB - 1) / TB, TB>>>((const float*)pooled, l1w, l1b, l2w, l2b,
                                     (float*)d_out, g);
}